// round 8
// baseline (speedup 1.0000x reference)
#include <cuda_runtime.h>
#include <cstdint>

// ---------------------------------------------------------------------------
// Batched greedy nearest-neighbor (B=64, N=1000), latency-chain optimized.
//
// One 256-thread CTA per batch:
//   warp 0  : the sequential greedy chain. 8 float4 slots/lane (N<=1024 in
//             one warp). Per step: 8x asm LDG.128 (one round-trip), masked
//             elems get sign bit set (unsigned-max), depth-5 pairwise tree
//             argmin on (fbits, elem) with ties->lowest col, then
//             REDUX min(fbits) + REDUX min(col). No smem, no barriers.
//   warps 1-7: prefetch all this batch's reachable rows ({unmasked}) into
//             L2 (one 128B line per lane = one row per iteration), then exit.
//             Overlaps with the chain; L2 also stays warm across graph
//             replays (L2 not flushed per launch), so this is insurance.
// Active-step count C = popcount(~mask0); tail is pad fill. Output = f32.
// ---------------------------------------------------------------------------

#define MK_BYTE  0   // u8 bool
#define MK_WORD  1   // i32 / f32 (word != 0 is truth)
#define MK_DWORD 2   // i64 (low word at stride 2)
#define MK_HALF  3   // u16 / bf16 / f16

#define SK_I32 0
#define SK_I64 1
#define SK_F32 2

__device__ int g_mask_kind, g_start_kind, g_pad;

__global__ void detect_kernel(const unsigned int* __restrict__ mw, int m_nwords,
                              const unsigned int* __restrict__ sw, int s_nwords,
                              const unsigned int* __restrict__ pw, int has_pad,
                              int N)
{
    __shared__ int vi_word, vi_dword, vi_half, s_odd_nz, s_small_int, s_nonfloat;
    if (threadIdx.x == 0) {
        vi_word = 0; vi_dword = 0; vi_half = 0;
        s_odd_nz = 0; s_small_int = 0; s_nonfloat = 0;
    }
    __syncthreads();

    int a = 0, b = 0, c = 0;
    #pragma unroll 4
    for (int i = threadIdx.x; i < m_nwords; i += blockDim.x) {
        unsigned int v = mw[i];
        if (v != 0u && v != 1u && v != 0x3F800000u) a = 1;
        if ((i & 1) ? (v != 0u) : (v > 1u)) b = 1;
        unsigned int h0 = v & 0xFFFFu, h1 = v >> 16;
        if (!(h0 == 0u || h0 == 1u || h0 == 0x3F80u || h0 == 0x3C00u)) c = 1;
        if (!(h1 == 0u || h1 == 1u || h1 == 0x3F80u || h1 == 0x3C00u)) c = 1;
    }
    if (a) vi_word = 1;
    if (b) vi_dword = 1;
    if (c) vi_half = 1;

    int o = 0, si = 0, nf = 0;
    for (int i = threadIdx.x; i < s_nwords; i += blockDim.x) {
        unsigned int v = sw[i];
        if ((i & 1) && v != 0u) o = 1;
        if (v >= 1u && v < 0x01000000u) si = 1;
        if (!(v == 0u || (v >= 0x30000000u && v < 0x45000000u))) nf = 1;
    }
    if (o)  s_odd_nz = 1;
    if (si) s_small_int = 1;
    if (nf) s_nonfloat = 1;
    __syncthreads();

    if (threadIdx.x == 0) {
        int mk;
        if      (!vi_word)  mk = MK_WORD;
        else if (!vi_dword) mk = MK_DWORD;
        else if (!vi_half)  mk = MK_HALF;
        else                mk = MK_BYTE;
        g_mask_kind = mk;

        int sk;
        if      (!s_odd_nz && s_nwords >= 2)  sk = SK_I64;
        else if (!s_nonfloat && !s_small_int) sk = SK_F32;
        else                                  sk = SK_I32;
        g_start_kind = sk;

        int pad = N;
        if (has_pad) {
            unsigned int p0 = pw[0];
            if (p0 < 0x01000000u) {
                pad = (int)p0;
                if (p0 == 0u) {
                    unsigned int p1 = pw[1];
                    if (p1 >= 0x3FF00000u && p1 < 0x42000000u)
                        pad = (int)__hiloint2double((int)p1, 0);
                }
            } else {
                float f = __uint_as_float(p0);
                if (f >= 0.0f && f < 16777216.0f) pad = (int)f;
            }
        }
        g_pad = pad;
    }
}

__device__ __forceinline__ bool mask_at(const void* mask, int mk, int off) {
    if (mk == MK_WORD)  return ((const unsigned int*)mask)[off]      != 0u;
    if (mk == MK_BYTE)  return ((const unsigned char*)mask)[off]     != 0u;
    if (mk == MK_HALF)  return ((const unsigned short*)mask)[off]    != 0u;
    return ((const unsigned int*)mask)[2 * off] != 0u;                 // i64
}

__device__ __forceinline__ int read_start(const void* start_idx, int sk, int b) {
    const int* s32 = (const int*)start_idx;
    if (sk == SK_I64) return s32[2 * b];
    if (sk == SK_F32) return (int)((const float*)start_idx)[b];
    return s32[b];
}

__device__ __forceinline__ float4 ldg128_nc(const float* p) {
    float4 v;
    asm volatile("ld.global.nc.v4.f32 {%0,%1,%2,%3}, [%4];"
                 : "=f"(v.x), "=f"(v.y), "=f"(v.z), "=f"(v.w)
                 : "l"(p));
    return v;
}

__global__ __launch_bounds__(256, 1)
void greedy_nn_kernel(const float* __restrict__ dist,
                      const void*  __restrict__ mask,
                      const void*  __restrict__ start_idx,
                      float*       __restrict__ out,
                      int B, int N, int write_len)
{
    const int b    = blockIdx.x;
    const int tid  = threadIdx.x;
    const int lane = tid & 31;
    const int wid  = tid >> 5;
    const int mk   = g_mask_kind;
    const float* dbase = dist + (size_t)b * N * N;
    const int row_bytes = 4 * N;

    // ---- warps 1..7: L2 prefetch of this batch's unmasked rows, then exit -
    if (wid != 0) {
        for (int row = wid - 1; row < N; row += 7) {
            if (!mask_at(mask, mk, b * N + row)) {
                uintptr_t p0 = (uintptr_t)(dbase + (size_t)row * N);
                uintptr_t first = p0 & ~(uintptr_t)127;
                uintptr_t last  = (p0 + row_bytes - 1) & ~(uintptr_t)127;
                int nlines = (int)((last - first) >> 7) + 1;     // <= 33
                if (lane < nlines)
                    asm volatile("prefetch.global.L2 [%0];"
                                 :: "l"(first + ((uintptr_t)lane << 7)));
                if (lane + 32 < nlines)
                    asm volatile("prefetch.global.L2 [%0];"
                                 :: "l"(first + ((uintptr_t)(lane + 32) << 7)));
            }
        }
        return;
    }

    // ======================= warp 0: the chain =============================
    const int nf4 = N >> 2;

    // visited bits: elem e = 4*q + r -> col 4*(lane + 32q) + r
    unsigned int m = 0;
    #pragma unroll
    for (int q = 0; q < 8; q++) {
        #pragma unroll
        for (int r = 0; r < 4; r++) {
            int col = 4 * (lane + 32 * q) + r;
            bool mb = true;                        // out-of-range -> visited
            if (col < N) mb = mask_at(mask, mk, b * N + col);
            if (mb) m |= 1u << (q * 4 + r);
        }
    }

    const int C = (int)__reduce_add_sync(0xffffffffu, 32u - (unsigned)__popc(m));

    int point = read_start(start_idx, g_start_kind, b);
    if (point < 0) point = 0;
    if (point >= N) point = N - 1;

    float* pred = out + (size_t)b * N;
    const float padf = (float)g_pad;

    for (int t = 0; t < C; t++) {
        const float* rp = dbase + (size_t)point * N;

        // 8 batched LDG.128 (asm: cannot be sunk/split); one round-trip
        float4 v[8];
        #pragma unroll
        for (int q = 0; q < 8; q++) {
            int f = lane + 32 * q;
            if (f < nf4) {
                v[q] = ldg128_nc(rp + 4 * f);
            } else {
                v[q] = make_float4(0.f, 0.f, 0.f, 0.f);
                if (f == nf4 && (N & 3)) {         // partial tail group
                    float* pv = (float*)&v[q];
                    #pragma unroll
                    for (int r = 0; r < 4; r++)
                        if (4 * f + r < N) pv[r] = __ldg(rp + 4 * f + r);
                }
            }
        }

        // keys: fbits with sign bit forced for masked (unsigned-max);
        // all real distances are non-negative so unsigned order == float order
        unsigned int kf[32], ke[32];
        #pragma unroll
        for (int e = 0; e < 32; e++) {
            const float* pv = (const float*)&v[e >> 2];
            unsigned int fb = __float_as_uint(pv[e & 3]);
            fb |= ((m >> e) & 1u) << 31;
            kf[e] = fb;
            ke[e] = (unsigned)e;
        }
        // depth-5 pairwise tree; strict '<' on right keeps LEFT (lower col)
        // on ties; leaves are in ascending col order.
        #pragma unroll
        for (int sdist = 1; sdist < 32; sdist <<= 1) {
            #pragma unroll
            for (int i = 0; i < 32; i += 2 * sdist) {
                if (kf[i + sdist] < kf[i]) {
                    kf[i] = kf[i + sdist];
                    ke[i] = ke[i + sdist];
                }
            }
        }
        const unsigned int bf = kf[0];
        const unsigned int mycol =
            4u * (unsigned)lane + ((ke[0] >> 2) << 7) + (ke[0] & 3u);

        unsigned int wmin = __reduce_min_sync(0xffffffffu, bf);
        unsigned int colc = (bf == wmin) ? mycol : 0xFFFFFFFFu;
        unsigned int idx  = __reduce_min_sync(0xffffffffu, colc);

        if (lane == 0) pred[t] = (float)idx;

        int f = (int)idx >> 2;                     // owner lane marks visited
        if ((f & 31) == lane)
            m |= 1u << (((f >> 5) << 2) | ((int)idx & 3));
        point = (int)idx;
    }

    // pad tail + pred_len
    for (int t = C + lane; t < N; t += 32) pred[t] = padf;
    if (write_len && lane == 0) out[(size_t)B * N + b] = (float)C;
}

extern "C" void kernel_launch(void* const* d_in, const int* in_sizes, int n_in,
                              void* d_out, int out_size)
{
    // ---- identify inputs by element count (order-proof) -------------------
    int di = 0, mi = -1, si = -1, pi = -1;
    for (int i = 1; i < n_in; i++)
        if (in_sizes[i] > in_sizes[di]) di = i;            // distance: largest
    for (int i = 0; i < n_in; i++) {
        if (i == di) continue;
        if (pi < 0 || in_sizes[i] < in_sizes[pi]) pi = i;  // pad: smallest
    }
    for (int i = 0; i < n_in; i++) {
        if (i == di || i == pi) continue;
        if (mi < 0) { mi = i; continue; }
        si = i;
    }
    if (si >= 0 && in_sizes[si] > in_sizes[mi]) { int t = mi; mi = si; si = t; }
    if (si < 0) { si = pi; pi = -1; }                      // only 3 inputs

    const float* dist  = (const float*)d_in[di];
    const void*  mask  = d_in[mi];
    const void*  start = d_in[si];
    const void*  padp  = (pi >= 0) ? d_in[pi] : nullptr;

    const int B = in_sizes[si];
    const int N = in_sizes[mi] / B;

    // classification needs only a few KB of evidence
    int m_nwords = in_sizes[mi] / 4;
    if (m_nwords > 2048) m_nwords = 2048;
    int s_nwords = in_sizes[si];
    detect_kernel<<<1, 256>>>((const unsigned int*)mask, m_nwords,
                              (const unsigned int*)start, s_nwords,
                              padp ? (const unsigned int*)padp
                                   : (const unsigned int*)start,
                              padp ? 1 : 0, N);

    int write_len = (out_size >= B * N + B) ? 1 : 0;
    greedy_nn_kernel<<<B, 256>>>(dist, mask, start, (float*)d_out,
                                 B, N, write_len);
}

// round 9
// speedup vs baseline: 1.2697x; 1.2697x over previous
#include <cuda_runtime.h>
#include <cstdint>

// ---------------------------------------------------------------------------
// Batched greedy nearest-neighbor (B=64, N=1000).
//
// Key bottleneck history: the chain re-reads ~128MB of reachable rows per
// replay; 128MB > 126MB L2 => LRU thrash => every step pays DRAM latency.
// Fix: build a u16 shadow (top 16 bits of f32, monotone) of only the
// reachable rows (~64MB, fits L2). Chain argmin runs on the shadow with a
// (val16<<16)|col key (one u32 REDUX gives min value + lowest col). Exact-
// ness: true min always truncates to the min val16; if multiple unmasked
// cols share it (rare, ~1%/step), a slow path reads their exact f32s.
//
// Kernels: detect (dtype sniffing, capped) -> build_shadow (streaming f32
// reads via __ldcs, u16 writes stay L2-resident) -> chain (128 thr/batch,
// 1 LDG.128/thread/step, REDUX + 4-warp smem combine, 1 syncthreads/step).
// Fallback to direct-f32 chain (proven R5) for non-conforming shapes.
// ---------------------------------------------------------------------------

#define MK_BYTE  0
#define MK_WORD  1
#define MK_DWORD 2
#define MK_HALF  3

#define SK_I32 0
#define SK_I64 1
#define SK_F32 2

#define SHADOW_CAP 64000000ULL
#define BUILD_CTAS 10

__device__ int g_mask_kind, g_start_kind, g_pad;
__device__ unsigned short g_shadow[SHADOW_CAP];    // 128MB static scratch

__global__ void detect_kernel(const unsigned int* __restrict__ mw, int m_nwords,
                              const unsigned int* __restrict__ sw, int s_nwords,
                              const unsigned int* __restrict__ pw, int has_pad,
                              int N)
{
    __shared__ int vi_word, vi_dword, vi_half, s_odd_nz, s_small_int, s_nonfloat;
    if (threadIdx.x == 0) {
        vi_word = 0; vi_dword = 0; vi_half = 0;
        s_odd_nz = 0; s_small_int = 0; s_nonfloat = 0;
    }
    __syncthreads();

    int a = 0, b = 0, c = 0;
    #pragma unroll 4
    for (int i = threadIdx.x; i < m_nwords; i += blockDim.x) {
        unsigned int v = mw[i];
        if (v != 0u && v != 1u && v != 0x3F800000u) a = 1;
        if ((i & 1) ? (v != 0u) : (v > 1u)) b = 1;
        unsigned int h0 = v & 0xFFFFu, h1 = v >> 16;
        if (!(h0 == 0u || h0 == 1u || h0 == 0x3F80u || h0 == 0x3C00u)) c = 1;
        if (!(h1 == 0u || h1 == 1u || h1 == 0x3F80u || h1 == 0x3C00u)) c = 1;
    }
    if (a) vi_word = 1;
    if (b) vi_dword = 1;
    if (c) vi_half = 1;

    int o = 0, si = 0, nf = 0;
    for (int i = threadIdx.x; i < s_nwords; i += blockDim.x) {
        unsigned int v = sw[i];
        if ((i & 1) && v != 0u) o = 1;
        if (v >= 1u && v < 0x01000000u) si = 1;
        if (!(v == 0u || (v >= 0x30000000u && v < 0x45000000u))) nf = 1;
    }
    if (o)  s_odd_nz = 1;
    if (si) s_small_int = 1;
    if (nf) s_nonfloat = 1;
    __syncthreads();

    if (threadIdx.x == 0) {
        int mk;
        if      (!vi_word)  mk = MK_WORD;
        else if (!vi_dword) mk = MK_DWORD;
        else if (!vi_half)  mk = MK_HALF;
        else                mk = MK_BYTE;
        g_mask_kind = mk;

        int sk;
        if      (!s_odd_nz && s_nwords >= 2)  sk = SK_I64;
        else if (!s_nonfloat && !s_small_int) sk = SK_F32;
        else                                  sk = SK_I32;
        g_start_kind = sk;

        int pad = N;
        if (has_pad) {
            unsigned int p0 = pw[0];
            if (p0 < 0x01000000u) {
                pad = (int)p0;
                if (p0 == 0u) {
                    unsigned int p1 = pw[1];
                    if (p1 >= 0x3FF00000u && p1 < 0x42000000u)
                        pad = (int)__hiloint2double((int)p1, 0);
                }
            } else {
                float f = __uint_as_float(p0);
                if (f >= 0.0f && f < 16777216.0f) pad = (int)f;
            }
        }
        g_pad = pad;
    }
}

__device__ __forceinline__ bool mask_at(const void* mask, int mk, int off) {
    if (mk == MK_WORD)  return ((const unsigned int*)mask)[off]      != 0u;
    if (mk == MK_BYTE)  return ((const unsigned char*)mask)[off]     != 0u;
    if (mk == MK_HALF)  return ((const unsigned short*)mask)[off]    != 0u;
    return ((const unsigned int*)mask)[2 * off] != 0u;                 // i64
}

__device__ __forceinline__ int read_start(const void* start_idx, int sk, int b) {
    const int* s32 = (const int*)start_idx;
    if (sk == SK_I64) return s32[2 * b];
    if (sk == SK_F32) return (int)((const float*)start_idx)[b];
    return s32[b];
}

// ---- build u16 shadow of reachable rows ({start} U unmasked) --------------
__global__ __launch_bounds__(256)
void build_shadow_kernel(const float* __restrict__ dist,
                         const void*  __restrict__ mask,
                         const void*  __restrict__ start_idx,
                         int B, int N)
{
    const int b  = blockIdx.x / BUILD_CTAS;
    const int q  = blockIdx.x % BUILD_CTAS;
    const int mk = g_mask_kind;
    const int nf4 = N >> 2;

    int sb = read_start(start_idx, g_start_kind, b);
    if (sb < 0) sb = 0;
    if (sb >= N) sb = N - 1;

    for (int r = q; r < N; r += BUILD_CTAS) {
        if (r != sb && mask_at(mask, mk, b * N + r)) continue;
        const float4* src = (const float4*)(dist + (size_t)(b * N + r) * N);
        ushort4* dst = (ushort4*)(g_shadow + (size_t)(b * N + r) * N);
        for (int i = threadIdx.x; i < nf4; i += blockDim.x) {
            float4 v = __ldcs(&src[i]);            // evict-first streaming
            ushort4 o;
            o.x = (unsigned short)(__float_as_uint(v.x) >> 16);
            o.y = (unsigned short)(__float_as_uint(v.y) >> 16);
            o.z = (unsigned short)(__float_as_uint(v.z) >> 16);
            o.w = (unsigned short)(__float_as_uint(v.w) >> 16);
            dst[i] = o;                            // stays L2-resident
        }
    }
}

// ---- chain on the shadow (N%8==0, N<=1024) --------------------------------
__global__ __launch_bounds__(128, 1)
void greedy_shadow_kernel(const float* __restrict__ dist,
                          const void*  __restrict__ mask,
                          const void*  __restrict__ start_idx,
                          float*       __restrict__ out,
                          int B, int N, int write_len)
{
    __shared__ unsigned int sbuf[2][4];
    __shared__ unsigned long long sslow[2][4];
    __shared__ int scnt[4];

    const int b    = blockIdx.x;
    const int tid  = threadIdx.x;
    const int lane = tid & 31;
    const int wid  = tid >> 5;
    const int mk   = g_mask_kind;
    const int ng8  = N >> 3;                       // u16x8 groups (=125)
    const float padf = (float)g_pad;

    // visited bits: thread owns cols 8*tid .. 8*tid+7 (bit r)
    unsigned int m = 0xFF;                         // default all visited
    if (tid < ng8) {
        m = 0;
        #pragma unroll
        for (int r = 0; r < 8; r++)
            if (mask_at(mask, mk, b * N + 8 * tid + r)) m |= 1u << r;
    }

    {
        unsigned int cnt = (tid < ng8) ? (8u - (unsigned)__popc(m)) : 0u;
        cnt = __reduce_add_sync(0xffffffffu, cnt);
        if (lane == 0) scnt[wid] = (int)cnt;
    }
    __syncthreads();
    const int C = scnt[0] + scnt[1] + scnt[2] + scnt[3];

    int point = read_start(start_idx, g_start_kind, b);
    if (point < 0) point = 0;
    if (point >= N) point = N - 1;

    const float* dbase = dist + (size_t)b * N * N;
    float* pred = out + (size_t)b * N;

    for (int t = 0; t < C; t++) {
        const unsigned short* srow = g_shadow + (size_t)(b * N + point) * N;

        // one LDG.128 per thread: 8 u16 values
        unsigned int h[8];
        if (tid < ng8) {
            uint4 d = *(const uint4*)(srow + 8 * tid);
            h[0] = d.x & 0xFFFFu; h[1] = d.x >> 16;
            h[2] = d.y & 0xFFFFu; h[3] = d.y >> 16;
            h[4] = d.z & 0xFFFFu; h[5] = d.z >> 16;
            h[6] = d.w & 0xFFFFu; h[7] = d.w >> 16;
        }

        // keys (val16<<16)|col; masked/idle -> max
        unsigned int kmin = 0xFFFFFFFFu;
        unsigned int key[8];
        #pragma unroll
        for (int r = 0; r < 8; r++) {
            unsigned int k = 0xFFFFFFFFu;
            if (tid < ng8 && !((m >> r) & 1u))
                k = (h[r] << 16) | (unsigned)(8 * tid + r);
            key[r] = k;
            kmin = k < kmin ? k : kmin;
        }

        unsigned int wkey = __reduce_min_sync(0xffffffffu, kmin);
        unsigned int vminw = wkey >> 16;

        // per-warp multiplicity of vminw among unmasked elems
        unsigned int cnt = 0;
        #pragma unroll
        for (int r = 0; r < 8; r++)
            cnt += (key[r] != 0xFFFFFFFFu && (key[r] >> 16) == vminw);
        unsigned int wcnt = __reduce_add_sync(0xffffffffu, cnt);

        // pack: val16 in [31:16], dup flag in bit 15, col (<=1023) in [9:0]
        if (lane == 0)
            sbuf[t & 1][wid] = wkey | ((wcnt > 1) ? 0x8000u : 0u);
        __syncthreads();

        unsigned int w0 = sbuf[t & 1][0], w1 = sbuf[t & 1][1];
        unsigned int w2 = sbuf[t & 1][2], w3 = sbuf[t & 1][3];

        unsigned int v0 = w0 >> 16, v1 = w1 >> 16, v2 = w2 >> 16, v3 = w3 >> 16;
        unsigned int vmin = min(min(v0, v1), min(v2, v3));
        int nmin = (v0 == vmin) + (v1 == vmin) + (v2 == vmin) + (v3 == vmin);
        // winner among val-min warps: lowest col
        unsigned int bcol = 0xFFFFFFFFu, bflag = 0;
        #pragma unroll
        for (int i = 0; i < 4; i++) {
            unsigned int wi = (i == 0) ? w0 : (i == 1) ? w1 : (i == 2) ? w2 : w3;
            if ((wi >> 16) == vmin) {
                unsigned int col = wi & 0x3FFu;
                if (col < bcol) { bcol = col; bflag = (wi >> 15) & 1u; }
            }
        }
        bool tie = (nmin > 1) || (bflag != 0);

        unsigned int idx;
        if (!tie) {
            idx = bcol;
        } else {
            // slow path (rare): exact f32 compare among val16==vmin candidates
            const float* rp = dbase + (size_t)point * N;
            unsigned int bb = 0xFFFFFFFFu, bc = 0x3FFu;
            #pragma unroll
            for (int r = 0; r < 8; r++) {
                if (key[r] != 0xFFFFFFFFu && (key[r] >> 16) == vmin) {
                    unsigned int fb = __float_as_uint(__ldg(rp + 8 * tid + r));
                    if (fb < bb) { bb = fb; bc = (unsigned)(8 * tid + r); }
                }
            }
            unsigned int wf = __reduce_min_sync(0xffffffffu, bb);
            unsigned int wc = __reduce_min_sync(0xffffffffu,
                                  (bb == wf) ? bc : 0xFFFFFFFFu);
            if (lane == 0)
                sslow[t & 1][wid] = ((unsigned long long)wf << 32) | wc;
            __syncthreads();
            unsigned long long k0 = sslow[t & 1][0], k1 = sslow[t & 1][1];
            unsigned long long k2 = sslow[t & 1][2], k3 = sslow[t & 1][3];
            unsigned long long ka = k0 < k1 ? k0 : k1;
            unsigned long long kb = k2 < k3 ? k2 : k3;
            unsigned long long kk = ka < kb ? ka : kb;
            idx = (unsigned int)kk;
        }

        if (tid == 0) pred[t] = (float)idx;
        if ((int)(idx >> 3) == tid) m |= 1u << (idx & 7u);
        point = (int)idx;
    }

    for (int t = C + tid; t < N; t += 128) pred[t] = padf;
    if (write_len && tid == 0) out[(size_t)B * N + b] = (float)C;
}

// ---- fallback: direct-f32 chain (proven R5 design) ------------------------
__device__ __forceinline__ float4 ldg128_nc(const float* p) {
    float4 v;
    asm volatile("ld.global.nc.v4.f32 {%0,%1,%2,%3}, [%4];"
                 : "=f"(v.x), "=f"(v.y), "=f"(v.z), "=f"(v.w)
                 : "l"(p));
    return v;
}

__global__ __launch_bounds__(128, 1)
void greedy_f32_kernel(const float* __restrict__ dist,
                       const void*  __restrict__ mask,
                       const void*  __restrict__ start_idx,
                       float*       __restrict__ out,
                       int B, int N, int write_len)
{
    __shared__ unsigned long long sbuf[2][4];
    __shared__ int scnt[4];

    const int b    = blockIdx.x;
    const int tid  = threadIdx.x;
    const int lane = tid & 31;
    const int wid  = tid >> 5;
    const int mk   = g_mask_kind;
    const float padf = (float)g_pad;
    const int nf4  = N >> 2;
    const unsigned int BIGBITS = 0x49742400u;

    const bool v0 = (tid       < nf4);
    const bool v1 = (tid + 128 < nf4);

    unsigned int m = 0;
    #pragma unroll
    for (int s = 0; s < 2; s++) {
        #pragma unroll
        for (int r = 0; r < 4; r++) {
            int col = 4 * (tid + 128 * s) + r;
            bool mb = true;
            if (col < N) mb = mask_at(mask, mk, b * N + col);
            if (mb) m |= 1u << (s * 4 + r);
        }
    }

    {
        unsigned int cnt = 8u - (unsigned)__popc(m);
        cnt = __reduce_add_sync(0xffffffffu, cnt);
        if (lane == 0) scnt[wid] = (int)cnt;
    }
    __syncthreads();
    const int C = scnt[0] + scnt[1] + scnt[2] + scnt[3];

    int point = read_start(start_idx, g_start_kind, b);
    if (point < 0) point = 0;
    if (point >= N) point = N - 1;

    const float* dbase = dist + (size_t)b * N * N;
    float* pred = out + (size_t)b * N;

    for (int t = 0; t < C; t++) {
        const float* rp = dbase + (size_t)point * N;

        float4 a = v0 ? ldg128_nc(rp + 4 * tid)
                      : make_float4(1e6f, 1e6f, 1e6f, 1e6f);
        float4 c = v1 ? ldg128_nc(rp + 4 * (tid + 128))
                      : make_float4(1e6f, 1e6f, 1e6f, 1e6f);

        unsigned int bb = BIGBITS, bc = 0;
        const float* pa = (const float*)&a;
        const float* pc = (const float*)&c;
        #pragma unroll
        for (int r = 0; r < 4; r++) {
            unsigned int fb = ((m >> r) & 1u) ? BIGBITS : __float_as_uint(pa[r]);
            if (fb < bb) { bb = fb; bc = 4 * tid + r; }
        }
        #pragma unroll
        for (int r = 0; r < 4; r++) {
            unsigned int fb = ((m >> (4 + r)) & 1u) ? BIGBITS : __float_as_uint(pc[r]);
            if (fb < bb) { bb = fb; bc = 4 * (tid + 128) + r; }
        }

        unsigned int wmin = __reduce_min_sync(0xffffffffu, bb);
        unsigned int colc = (bb == wmin) ? bc : 0xFFFFFFFFu;
        unsigned int wcol = __reduce_min_sync(0xffffffffu, colc);

        if (lane == 0)
            sbuf[t & 1][wid] = ((unsigned long long)wmin << 32) | wcol;
        __syncthreads();
        unsigned long long k0 = sbuf[t & 1][0], k1 = sbuf[t & 1][1];
        unsigned long long k2 = sbuf[t & 1][2], k3 = sbuf[t & 1][3];
        unsigned long long ka = k0 < k1 ? k0 : k1;
        unsigned long long kb = k2 < k3 ? k2 : k3;
        unsigned long long k  = ka < kb ? ka : kb;

        int idx = (int)(unsigned int)k;
        if (tid == 0) pred[t] = (float)idx;

        int f = idx >> 2;
        if ((f & 127) == tid)
            m |= 1u << (((f >> 7) << 2) | (idx & 3));
        point = idx;
    }

    for (int t = C + tid; t < N; t += 128) pred[t] = padf;
    if (write_len && tid == 0) out[(size_t)B * N + b] = (float)C;
}

extern "C" void kernel_launch(void* const* d_in, const int* in_sizes, int n_in,
                              void* d_out, int out_size)
{
    // ---- identify inputs by element count (order-proof) -------------------
    int di = 0, mi = -1, si = -1, pi = -1;
    for (int i = 1; i < n_in; i++)
        if (in_sizes[i] > in_sizes[di]) di = i;
    for (int i = 0; i < n_in; i++) {
        if (i == di) continue;
        if (pi < 0 || in_sizes[i] < in_sizes[pi]) pi = i;
    }
    for (int i = 0; i < n_in; i++) {
        if (i == di || i == pi) continue;
        if (mi < 0) { mi = i; continue; }
        si = i;
    }
    if (si >= 0 && in_sizes[si] > in_sizes[mi]) { int t = mi; mi = si; si = t; }
    if (si < 0) { si = pi; pi = -1; }

    const float* dist  = (const float*)d_in[di];
    const void*  mask  = d_in[mi];
    const void*  start = d_in[si];
    const void*  padp  = (pi >= 0) ? d_in[pi] : nullptr;

    const int B = in_sizes[si];
    const int N = in_sizes[mi] / B;

    int m_nwords = in_sizes[mi] / 4;
    if (m_nwords > 2048) m_nwords = 2048;
    int s_nwords = in_sizes[si];
    detect_kernel<<<1, 256>>>((const unsigned int*)mask, m_nwords,
                              (const unsigned int*)start, s_nwords,
                              padp ? (const unsigned int*)padp
                                   : (const unsigned int*)start,
                              padp ? 1 : 0, N);

    int write_len = (out_size >= B * N + B) ? 1 : 0;

    bool shadow_ok = (N % 8 == 0) && (N >= 8) && (N <= 1024) &&
                     ((unsigned long long)B * N * N <= SHADOW_CAP);
    if (shadow_ok) {
        build_shadow_kernel<<<B * BUILD_CTAS, 256>>>(dist, mask, start, B, N);
        greedy_shadow_kernel<<<B, 128>>>(dist, mask, start, (float*)d_out,
                                         B, N, write_len);
    } else {
        greedy_f32_kernel<<<B, 128>>>(dist, mask, start, (float*)d_out,
                                      B, N, write_len);
    }
}

// round 11
// speedup vs baseline: 1.4901x; 1.1736x over previous
#include <cuda_runtime.h>
#include <cstdint>

// ---------------------------------------------------------------------------
// Batched greedy nearest-neighbor (B=64, N=1000).
//
// Insight: a greedy step needs only "first unvisited col in this row's exact
// (value,col) order". Precompute per reachable row the top-16 cols in exact
// sortable-f32 order (build kernel, bandwidth-bound). Chain: prefix in SMEM
// (32B/row), visited bitmap in warp registers; step = LDS + SHFL + REDUX
// (~60ns). If all 16 candidates visited (rare, late steps) -> exact full-row
// f32 fallback. Non-conforming shapes -> proven direct-f32 chain.
// ---------------------------------------------------------------------------

#define MK_BYTE  0
#define MK_WORD  1
#define MK_DWORD 2
#define MK_HALF  3

#define SK_I32 0
#define SK_I64 1
#define SK_F32 2

#define K_PREF 16
#define CAND_CAP 256

__device__ int g_mask_kind, g_start_kind, g_pad;
__device__ unsigned short g_prefix[16777216];   // 32MB: up to 1M rows

__global__ void detect_kernel(const unsigned int* __restrict__ mw, int m_nwords,
                              const unsigned int* __restrict__ sw, int s_nwords,
                              const unsigned int* __restrict__ pw, int has_pad,
                              int N)
{
    __shared__ int vi_word, vi_dword, vi_half, s_odd_nz, s_small_int, s_nonfloat;
    if (threadIdx.x == 0) {
        vi_word = 0; vi_dword = 0; vi_half = 0;
        s_odd_nz = 0; s_small_int = 0; s_nonfloat = 0;
    }
    __syncthreads();

    int a = 0, b = 0, c = 0;
    #pragma unroll 4
    for (int i = threadIdx.x; i < m_nwords; i += blockDim.x) {
        unsigned int v = mw[i];
        if (v != 0u && v != 1u && v != 0x3F800000u) a = 1;
        if ((i & 1) ? (v != 0u) : (v > 1u)) b = 1;
        unsigned int h0 = v & 0xFFFFu, h1 = v >> 16;
        if (!(h0 == 0u || h0 == 1u || h0 == 0x3F80u || h0 == 0x3C00u)) c = 1;
        if (!(h1 == 0u || h1 == 1u || h1 == 0x3F80u || h1 == 0x3C00u)) c = 1;
    }
    if (a) vi_word = 1;
    if (b) vi_dword = 1;
    if (c) vi_half = 1;

    int o = 0, si = 0, nf = 0;
    for (int i = threadIdx.x; i < s_nwords; i += blockDim.x) {
        unsigned int v = sw[i];
        if ((i & 1) && v != 0u) o = 1;
        if (v >= 1u && v < 0x01000000u) si = 1;
        if (!(v == 0u || (v >= 0x30000000u && v < 0x45000000u))) nf = 1;
    }
    if (o)  s_odd_nz = 1;
    if (si) s_small_int = 1;
    if (nf) s_nonfloat = 1;
    __syncthreads();

    if (threadIdx.x == 0) {
        int mk;
        if      (!vi_word)  mk = MK_WORD;
        else if (!vi_dword) mk = MK_DWORD;
        else if (!vi_half)  mk = MK_HALF;
        else                mk = MK_BYTE;
        g_mask_kind = mk;

        int sk;
        if      (!s_odd_nz && s_nwords >= 2)  sk = SK_I64;
        else if (!s_nonfloat && !s_small_int) sk = SK_F32;
        else                                  sk = SK_I32;
        g_start_kind = sk;

        int pad = N;
        if (has_pad) {
            unsigned int p0 = pw[0];
            if (p0 < 0x01000000u) {
                pad = (int)p0;
                if (p0 == 0u) {
                    unsigned int p1 = pw[1];
                    if (p1 >= 0x3FF00000u && p1 < 0x42000000u)
                        pad = (int)__hiloint2double((int)p1, 0);
                }
            } else {
                float f = __uint_as_float(p0);
                if (f >= 0.0f && f < 16777216.0f) pad = (int)f;
            }
        }
        g_pad = pad;
    }
}

__device__ __forceinline__ bool mask_at(const void* mask, int mk, int off) {
    if (mk == MK_WORD)  return ((const unsigned int*)mask)[off]      != 0u;
    if (mk == MK_BYTE)  return ((const unsigned char*)mask)[off]     != 0u;
    if (mk == MK_HALF)  return ((const unsigned short*)mask)[off]    != 0u;
    return ((const unsigned int*)mask)[2 * off] != 0u;                 // i64
}

__device__ __forceinline__ int read_start(const void* start_idx, int sk, int b) {
    const int* s32 = (const int*)start_idx;
    if (sk == SK_I64) return s32[2 * b];
    if (sk == SK_F32) return (int)((const float*)start_idx)[b];
    return s32[b];
}

// monotone float -> u32 order transform (handles sign; distances are >= 0)
__device__ __forceinline__ unsigned int sortable(float f) {
    unsigned int fb = __float_as_uint(f);
    return fb ^ ((((int)fb) >> 31) | 0x80000000u);
}

// ---- build exact top-K_PREF preference prefix per reachable row -----------
__global__ __launch_bounds__(128)
void build_prefix_kernel(const float* __restrict__ dist,
                         const void*  __restrict__ mask,
                         const void*  __restrict__ start_idx,
                         int B, int N)
{
    const int row_id = blockIdx.x;
    const int b = row_id / N;
    const int r = row_id % N;
    const int tid = threadIdx.x;
    const int mk = g_mask_kind;

    int sb = read_start(start_idx, g_start_kind, b);
    if (sb < 0) sb = 0;
    if (sb >= N) sb = N - 1;
    if (r != sb && mask_at(mask, mk, b * N + r)) return;   // unreachable row

    __shared__ int hist[256];
    __shared__ int s_bstar, s_total, s_cnt;
    __shared__ unsigned int   s_key[CAND_CAP];
    __shared__ unsigned short s_col[CAND_CAP];

    for (int i = tid; i < 256; i += 128) hist[i] = 0;
    if (tid == 0) s_cnt = 0;
    __syncthreads();

    const float* rp = dist + (size_t)b * N * N + (size_t)r * N;
    const int nf4 = N >> 2;

    unsigned int   skey[8];
    unsigned short cols[8];
    unsigned int   allow = 0;
    #pragma unroll
    for (int s = 0; s < 2; s++) {
        int f = tid + s * 128;
        #pragma unroll
        for (int r4 = 0; r4 < 4; r4++) { skey[s*4+r4] = 0xFFFFFFFFu; cols[s*4+r4] = 0xFFFF; }
        if (f < nf4) {
            float4 v = __ldcs((const float4*)rp + f);
            const float* pv = (const float*)&v;
            #pragma unroll
            for (int r4 = 0; r4 < 4; r4++) {
                int col = 4 * f + r4;
                int e = s * 4 + r4;
                skey[e] = sortable(pv[r4]);
                cols[e] = (unsigned short)col;
                if (!mask_at(mask, mk, b * N + col)) {
                    allow |= 1u << e;
                    atomicAdd(&hist[skey[e] >> 24], 1);
                }
            }
        }
    }
    __syncthreads();

    if (tid == 0) {
        int total = 0;
        for (int i = 0; i < 256; i++) total += hist[i];
        int want = total < K_PREF ? total : K_PREF;
        int cum = 0, bstar = 255;
        for (int i = 0; i < 256 && want > 0; i++) {
            cum += hist[i];
            if (cum >= want) { bstar = i; break; }
        }
        s_bstar = bstar;
        s_total = total;
    }
    __syncthreads();

    unsigned short* dst = g_prefix + (size_t)row_id * K_PREF;
    const int total = s_total;
    const int bstar = s_bstar;

    if (total == 0) {
        for (int i = tid; i < K_PREF; i += 128) dst[i] = 0xFFFF;
        return;
    }

    #pragma unroll
    for (int e = 0; e < 8; e++) {
        if (((allow >> e) & 1u) && (skey[e] >> 24) <= (unsigned)bstar) {
            int slot = atomicAdd(&s_cnt, 1);
            if (slot < CAND_CAP) { s_key[slot] = skey[e]; s_col[slot] = cols[e]; }
        }
    }
    __syncthreads();
    const int cnt = s_cnt;

    if (cnt > CAND_CAP) {                      // degenerate row: always-fallback
        for (int i = tid; i < K_PREF; i += 128) dst[i] = 0xFFFF;
        return;
    }

    // exact rank among candidates; ranks are unique -> fill slots [0, min(cnt,K))
    for (int i = tid; i < cnt; i += 128) {
        unsigned int   ki = s_key[i];
        unsigned short ci = s_col[i];
        int rank = 0;
        for (int j = 0; j < cnt; j++) {
            unsigned int kj = s_key[j];
            rank += (kj < ki) || (kj == ki && s_col[j] < ci);
        }
        if (rank < K_PREF) dst[rank] = ci;
    }
    const int kp = cnt < K_PREF ? cnt : K_PREF;
    for (int i = tid; i < K_PREF; i += 128)
        if (i >= kp) dst[i] = 0xFFFF;
}

// ---- the chain: prefix in SMEM, visited bitmap in warp-0 registers --------
__global__ __launch_bounds__(128, 1)
void greedy_prefix_kernel(const float* __restrict__ dist,
                          const void*  __restrict__ mask,
                          const void*  __restrict__ start_idx,
                          float*       __restrict__ out,
                          int B, int N, int write_len)
{
    __shared__ unsigned short s_pref[1024 * K_PREF];   // 32KB

    const int b    = blockIdx.x;
    const int tid  = threadIdx.x;
    const int lane = tid & 31;
    const int wid  = tid >> 5;

    // preload this batch's prefix table (N*K_PREF u16 = 2N uint4)
    {
        const uint4* src = (const uint4*)(g_prefix + (size_t)b * N * K_PREF);
        uint4* dst4 = (uint4*)s_pref;
        const int nvec = 2 * N;
        for (int i = tid; i < nvec; i += 128) dst4[i] = src[i];
    }
    __syncthreads();
    if (wid != 0) return;                       // warps 1-3 done

    const int mk = g_mask_kind;
    // visited bitmap in registers: lane j covers cols 32*lane .. 32*lane+31
    unsigned int word = 0;
    for (int j = 0; j < 32; j++) {
        int col = 32 * lane + j;
        bool vis = true;
        if (col < N) vis = mask_at(mask, mk, b * N + col);
        word |= (vis ? 1u : 0u) << j;
    }
    const int C = (int)__reduce_add_sync(0xffffffffu, (unsigned)__popc(~word));

    int point = read_start(start_idx, g_start_kind, b);
    if (point < 0) point = 0;
    if (point >= N) point = N - 1;

    const float* dbase = dist + (size_t)b * N * N;
    float* pred = out + (size_t)b * N;
    const float padf = (float)g_pad;

    for (int t = 0; t < C; t++) {
        unsigned int c = 0xFFFFu;
        if (lane < K_PREF) c = s_pref[point * K_PREF + lane];
        unsigned int w = __shfl_sync(0xffffffffu, word, (int)((c >> 5) & 31u));
        bool ok = (c < (unsigned)N) && !((w >> (c & 31u)) & 1u);
        unsigned int myk = ok ? (unsigned)lane : 64u;
        unsigned int ks = __reduce_min_sync(0xffffffffu, myk);

        unsigned int colstar;
        if (ks < 64u) {
            colstar = __shfl_sync(0xffffffffu, c, (int)ks);
        } else {
            // exact fallback: full-row scan (lane covers cols 32*lane..+31)
            const float* rp = dbase + (size_t)point * N;
            unsigned int bb = 0xFFFFFFFFu, bc = 0;
            #pragma unroll
            for (int q = 0; q < 8; q++) {
                int base = 32 * lane + 4 * q;
                if (base + 3 < N) {
                    float4 v = __ldg((const float4*)(rp + base));
                    const float* pv = (const float*)&v;
                    #pragma unroll
                    for (int r4 = 0; r4 < 4; r4++) {
                        if (!((word >> (4 * q + r4)) & 1u)) {
                            unsigned int sk = sortable(pv[r4]);
                            if (sk < bb) { bb = sk; bc = (unsigned)(base + r4); }
                        }
                    }
                }
            }
            unsigned int wm = __reduce_min_sync(0xffffffffu, bb);
            colstar = __reduce_min_sync(0xffffffffu,
                                        (bb == wm) ? bc : 0xFFFFFFFFu);
        }

        if (lane == 0) pred[t] = (float)colstar;
        if ((colstar >> 5) == (unsigned)lane) word |= 1u << (colstar & 31u);
        point = (int)colstar;
    }

    for (int t = C + lane; t < N; t += 32) pred[t] = padf;
    if (write_len && lane == 0) out[(size_t)B * N + b] = (float)C;
}

// ---- fallback for non-conforming shapes: proven direct-f32 chain ----------
__device__ __forceinline__ float4 ldg128_nc(const float* p) {
    float4 v;
    asm volatile("ld.global.nc.v4.f32 {%0,%1,%2,%3}, [%4];"
                 : "=f"(v.x), "=f"(v.y), "=f"(v.z), "=f"(v.w)
                 : "l"(p));
    return v;
}

__global__ __launch_bounds__(128, 1)
void greedy_f32_kernel(const float* __restrict__ dist,
                       const void*  __restrict__ mask,
                       const void*  __restrict__ start_idx,
                       float*       __restrict__ out,
                       int B, int N, int write_len)
{
    __shared__ unsigned long long sbuf[2][4];
    __shared__ int scnt[4];

    const int b    = blockIdx.x;
    const int tid  = threadIdx.x;
    const int lane = tid & 31;
    const int wid  = tid >> 5;
    const int mk   = g_mask_kind;
    const float padf = (float)g_pad;
    const int nf4  = N >> 2;
    const unsigned int BIGBITS = 0x49742400u;

    const bool v0 = (tid       < nf4);
    const bool v1 = (tid + 128 < nf4);

    unsigned int m = 0;
    #pragma unroll
    for (int s = 0; s < 2; s++) {
        #pragma unroll
        for (int r = 0; r < 4; r++) {
            int col = 4 * (tid + 128 * s) + r;
            bool mb = true;
            if (col < N) mb = mask_at(mask, mk, b * N + col);
            if (mb) m |= 1u << (s * 4 + r);
        }
    }

    {
        unsigned int cnt = 8u - (unsigned)__popc(m);
        cnt = __reduce_add_sync(0xffffffffu, cnt);
        if (lane == 0) scnt[wid] = (int)cnt;
    }
    __syncthreads();
    const int C = scnt[0] + scnt[1] + scnt[2] + scnt[3];

    int point = read_start(start_idx, g_start_kind, b);
    if (point < 0) point = 0;
    if (point >= N) point = N - 1;

    const float* dbase = dist + (size_t)b * N * N;
    float* pred = out + (size_t)b * N;

    for (int t = 0; t < C; t++) {
        const float* rp = dbase + (size_t)point * N;

        float4 a = v0 ? ldg128_nc(rp + 4 * tid)
                      : make_float4(1e6f, 1e6f, 1e6f, 1e6f);
        float4 c = v1 ? ldg128_nc(rp + 4 * (tid + 128))
                      : make_float4(1e6f, 1e6f, 1e6f, 1e6f);

        unsigned int bb = BIGBITS, bc = 0;
        const float* pa = (const float*)&a;
        const float* pc = (const float*)&c;
        #pragma unroll
        for (int r = 0; r < 4; r++) {
            unsigned int fb = ((m >> r) & 1u) ? BIGBITS : __float_as_uint(pa[r]);
            if (fb < bb) { bb = fb; bc = 4 * tid + r; }
        }
        #pragma unroll
        for (int r = 0; r < 4; r++) {
            unsigned int fb = ((m >> (4 + r)) & 1u) ? BIGBITS : __float_as_uint(pc[r]);
            if (fb < bb) { bb = fb; bc = 4 * (tid + 128) + r; }
        }

        unsigned int wmin = __reduce_min_sync(0xffffffffu, bb);
        unsigned int colc = (bb == wmin) ? bc : 0xFFFFFFFFu;
        unsigned int wcol = __reduce_min_sync(0xffffffffu, colc);

        if (lane == 0)
            sbuf[t & 1][wid] = ((unsigned long long)wmin << 32) | wcol;
        __syncthreads();
        unsigned long long k0 = sbuf[t & 1][0], k1 = sbuf[t & 1][1];
        unsigned long long k2 = sbuf[t & 1][2], k3 = sbuf[t & 1][3];
        unsigned long long ka = k0 < k1 ? k0 : k1;
        unsigned long long kb = k2 < k3 ? k2 : k3;
        unsigned long long k  = ka < kb ? ka : kb;

        int idx = (int)(unsigned int)k;
        if (tid == 0) pred[t] = (float)idx;

        int f = idx >> 2;
        if ((f & 127) == tid)
            m |= 1u << (((f >> 7) << 2) | (idx & 3));
        point = idx;
    }

    for (int t = C + tid; t < N; t += 128) pred[t] = padf;
    if (write_len && tid == 0) out[(size_t)B * N + b] = (float)C;
}

extern "C" void kernel_launch(void* const* d_in, const int* in_sizes, int n_in,
                              void* d_out, int out_size)
{
    // ---- identify inputs by element count (order-proof) -------------------
    int di = 0, mi = -1, si = -1, pi = -1;
    for (int i = 1; i < n_in; i++)
        if (in_sizes[i] > in_sizes[di]) di = i;
    for (int i = 0; i < n_in; i++) {
        if (i == di) continue;
        if (pi < 0 || in_sizes[i] < in_sizes[pi]) pi = i;
    }
    for (int i = 0; i < n_in; i++) {
        if (i == di || i == pi) continue;
        if (mi < 0) { mi = i; continue; }
        si = i;
    }
    if (si >= 0 && in_sizes[si] > in_sizes[mi]) { int t = mi; mi = si; si = t; }
    if (si < 0) { si = pi; pi = -1; }

    const float* dist  = (const float*)d_in[di];
    const void*  mask  = d_in[mi];
    const void*  start = d_in[si];
    const void*  padp  = (pi >= 0) ? d_in[pi] : nullptr;

    const int B = in_sizes[si];
    const int N = in_sizes[mi] / B;

    int m_nwords = in_sizes[mi] / 4;
    if (m_nwords > 2048) m_nwords = 2048;
    int s_nwords = in_sizes[si];
    detect_kernel<<<1, 256>>>((const unsigned int*)mask, m_nwords,
                              (const unsigned int*)start, s_nwords,
                              padp ? (const unsigned int*)padp
                                   : (const unsigned int*)start,
                              padp ? 1 : 0, N);

    int write_len = (out_size >= B * N + B) ? 1 : 0;

    bool fast_ok = (N % 4 == 0) && (N >= 4) && (N <= 1024) &&
                   ((long long)B * N <= 16777216LL / K_PREF);
    if (fast_ok) {
        build_prefix_kernel<<<B * N, 128>>>(dist, mask, start, B, N);
        greedy_prefix_kernel<<<B, 128>>>(dist, mask, start, (float*)d_out,
                                         B, N, write_len);
    } else {
        greedy_f32_kernel<<<B, 128>>>(dist, mask, start, (float*)d_out,
                                      B, N, write_len);
    }
}

// round 13
// speedup vs baseline: 2.0739x; 1.3918x over previous
#include <cuda_runtime.h>
#include <cstdint>

// ---------------------------------------------------------------------------
// Batched greedy nearest-neighbor (B=64, N=1000).
// prep:  per-batch visited bitmap (ballot), C, clamped start, dtype detect.
// build: one warp per reachable row; exact top-16 cols in (sortable-f32,col)
//        order via per-lane top-2 cache + 16x(REDUX,REDUX) extraction.
// chain: prefix in SMEM, visited bitmap in warp registers; step = LDS +
//        SHFL + REDUX + SHFL; prefix-exhausted -> exact full-row fallback.
// Non-conforming shapes -> proven direct-f32 chain.
// ---------------------------------------------------------------------------

#define MK_BYTE  0
#define MK_WORD  1
#define MK_DWORD 2
#define MK_HALF  3

#define SK_I32 0
#define SK_I64 1
#define SK_F32 2

#define K_PREF 16
#define MAXB   65536

__device__ int g_mask_kind, g_start_kind, g_pad;
__device__ unsigned short g_prefix[16777216];      // 32MB (<=1M rows)
__device__ unsigned int   g_bitmap[MAXB * 32];     // 8MB  per-batch visited
__device__ int            g_startc[MAXB];
__device__ int            g_C[MAXB];

__device__ __forceinline__ bool mask_at(const void* mask, int mk, int off) {
    if (mk == MK_WORD)  return ((const unsigned int*)mask)[off]      != 0u;
    if (mk == MK_BYTE)  return ((const unsigned char*)mask)[off]     != 0u;
    if (mk == MK_HALF)  return ((const unsigned short*)mask)[off]    != 0u;
    return ((const unsigned int*)mask)[2 * off] != 0u;                 // i64
}

__device__ __forceinline__ int read_start_k(const void* start_idx, int sk, int b) {
    const int* s32 = (const int*)start_idx;
    if (sk == SK_I64) return s32[2 * b];
    if (sk == SK_F32) return (int)((const float*)start_idx)[b];
    return s32[b];
}

__device__ __forceinline__ unsigned int sortable(float f) {
    unsigned int fb = __float_as_uint(f);
    return fb ^ ((((int)fb) >> 31) | 0x80000000u);
}

// detection core, shared by prep (per-CTA, smem result) and detect_kernel
__device__ void detect_core(const unsigned int* mw, int m_nwords,
                            const unsigned int* sw, int s_nwords,
                            const unsigned int* pw, int has_pad, int N,
                            int* out_mk, int* out_sk, int* out_pad,
                            int tid, int nthr,
                            int* sh /* 6 ints, zeroed, synced by caller */)
{
    int a = 0, b2 = 0, c = 0;
    for (int i = tid; i < m_nwords; i += nthr) {
        unsigned int v = mw[i];
        if (v != 0u && v != 1u && v != 0x3F800000u) a = 1;
        if ((i & 1) ? (v != 0u) : (v > 1u)) b2 = 1;
        unsigned int h0 = v & 0xFFFFu, h1 = v >> 16;
        if (!(h0 == 0u || h0 == 1u || h0 == 0x3F80u || h0 == 0x3C00u)) c = 1;
        if (!(h1 == 0u || h1 == 1u || h1 == 0x3F80u || h1 == 0x3C00u)) c = 1;
    }
    if (a)  sh[0] = 1;
    if (b2) sh[1] = 1;
    if (c)  sh[2] = 1;

    int o = 0, si = 0, nf = 0;
    for (int i = tid; i < s_nwords; i += nthr) {
        unsigned int v = sw[i];
        if ((i & 1) && v != 0u) o = 1;
        if (v >= 1u && v < 0x01000000u) si = 1;
        if (!(v == 0u || (v >= 0x30000000u && v < 0x45000000u))) nf = 1;
    }
    if (o)  sh[3] = 1;
    if (si) sh[4] = 1;
    if (nf) sh[5] = 1;
    __syncthreads();

    int mk;
    if      (!sh[0]) mk = MK_WORD;
    else if (!sh[1]) mk = MK_DWORD;
    else if (!sh[2]) mk = MK_HALF;
    else             mk = MK_BYTE;
    *out_mk = mk;

    int sk;
    if      (!sh[3] && s_nwords >= 2)  sk = SK_I64;
    else if (!sh[5] && !sh[4])         sk = SK_F32;
    else                               sk = SK_I32;
    *out_sk = sk;

    int pad = N;
    if (has_pad) {
        unsigned int p0 = pw[0];
        if (p0 < 0x01000000u) {
            pad = (int)p0;
            if (p0 == 0u) {
                unsigned int p1 = pw[1];
                if (p1 >= 0x3FF00000u && p1 < 0x42000000u)
                    pad = (int)__hiloint2double((int)p1, 0);
            }
        } else {
            float f = __uint_as_float(p0);
            if (f >= 0.0f && f < 16777216.0f) pad = (int)f;
        }
    }
    *out_pad = pad;
}

// ---- prep: per-batch bitmap + C + start (+ CTA0 publishes kinds) ----------
__global__ __launch_bounds__(256)
void prep_kernel(const void* __restrict__ mask,
                 const void* __restrict__ start_idx,
                 const unsigned int* __restrict__ pw, int has_pad,
                 int m_nwords, int s_nwords, int B, int N)
{
    __shared__ int sh[6];
    __shared__ unsigned int swords[32];
    __shared__ int scnt;
    const int b   = blockIdx.x;
    const int tid = threadIdx.x;
    const int lane = tid & 31;
    const int wid  = tid >> 5;

    if (tid < 6) sh[tid] = 0;
    if (tid == 0) scnt = 0;
    __syncthreads();

    int mk, sk, pad;
    detect_core((const unsigned int*)mask, m_nwords,
                (const unsigned int*)start_idx, s_nwords,
                pw, has_pad, N, &mk, &sk, &pad, tid, 256, sh);

    if (b == 0 && tid == 0) { g_mask_kind = mk; g_start_kind = sk; g_pad = pad; }

    // bitmap via ballot: pass p covers cols p*256 + tid
    #pragma unroll
    for (int p = 0; p < 4; p++) {
        int col = p * 256 + tid;
        bool vis = true;
        if (col < N) vis = mask_at(mask, mk, b * N + col);
        unsigned int w = __ballot_sync(0xffffffffu, vis);
        if (lane == 0) {
            swords[p * 8 + wid] = w;
            g_bitmap[b * 32 + p * 8 + wid] = w;
            atomicAdd(&scnt, __popc(~w));
        }
    }
    __syncthreads();
    (void)swords;

    if (tid == 0) {
        g_C[b] = scnt;
        int s = read_start_k(start_idx, sk, b);
        if (s < 0) s = 0;
        if (s >= N) s = N - 1;
        g_startc[b] = s;
    }
}

// ---- build: one warp per row, exact top-K_PREF --------------------------
__global__ __launch_bounds__(256)
void build_prefix_kernel(const float* __restrict__ dist, int B, int N)
{
    const int gw = blockIdx.x * 8 + (threadIdx.x >> 5);
    if (gw >= B * N) return;
    const int b = gw / N;
    const int r = gw % N;
    const int lane = threadIdx.x & 31;

    // reachable?
    unsigned int wr = g_bitmap[b * 32 + (r >> 5)];
    if (((wr >> (r & 31)) & 1u) && r != g_startc[b]) return;

    // per-lane mask bits for its 32 elems (once): elem e=4q+r4,
    // col=4*(lane+32q)+r4, word = 4q + (lane>>3), bit = (lane&7)*4 + r4
    unsigned int wl = g_bitmap[b * 32 + lane];
    unsigned int mymask = 0;
    {
        const int shift = (lane & 7) * 4;
        #pragma unroll
        for (int q = 0; q < 8; q++) {
            unsigned int w = __shfl_sync(0xffffffffu, wl, 4 * q + (lane >> 3));
            mymask |= ((w >> shift) & 0xFu) << (4 * q);
        }
    }

    // load row, make keys
    const float* rp = dist + (size_t)(b * N + r) * N;
    const int nf4 = N >> 2;
    unsigned int kv[32];
    #pragma unroll
    for (int q = 0; q < 8; q++) {
        int f = lane + 32 * q;
        if (f < nf4) {
            float4 v = __ldcs((const float4*)rp + f);
            const float* pv = (const float*)&v;
            #pragma unroll
            for (int r4 = 0; r4 < 4; r4++) {
                int e = 4 * q + r4;
                kv[e] = ((mymask >> e) & 1u) ? 0xFFFFFFFFu : sortable(pv[r4]);
            }
        } else {
            #pragma unroll
            for (int r4 = 0; r4 < 4; r4++) kv[4 * q + r4] = 0xFFFFFFFFu;
        }
    }

    // per-lane top-2 cache (ascending e, strict < => ties->lowest col)
    unsigned int taken = 0;
    unsigned int b0k = 0xFFFFFFFFu, b1k = 0xFFFFFFFFu;
    int b0e = -1, b1e = -1;
    #pragma unroll
    for (int e = 0; e < 32; e++) {
        unsigned int k = kv[e];
        if (k < b0k)      { b1k = b0k; b1e = b0e; b0k = k; b0e = e; }
        else if (k < b1k) { b1k = k;   b1e = e; }
    }

    unsigned int res = 0xFFFFu;
    for (int it = 0; it < K_PREF; it++) {
        unsigned int wmin = __reduce_min_sync(0xffffffffu, b0k);
        if (wmin == 0xFFFFFFFFu) break;
        // my candidate col (exact order: value then lowest col)
        unsigned int mycol = 0xFFFFFFFFu;
        if (b0k == wmin)
            mycol = 4u * (unsigned)(lane + 32 * (b0e >> 2)) + (unsigned)(b0e & 3);
        unsigned int cmin = __reduce_min_sync(0xffffffffu, mycol);
        if (lane == it) res = cmin;

        // winner lane pops
        if (((cmin >> 2) & 31u) == (unsigned)lane) {
            int e = (int)(((cmin >> 7) << 2) | (cmin & 3u));
            taken |= 1u << e;
            if (b1e >= 0) { b0k = b1k; b0e = b1e; b1e = -1; b1k = 0xFFFFFFFFu; }
            else {
                // rescan remaining
                b0k = 0xFFFFFFFFu; b0e = -1; b1k = 0xFFFFFFFFu; b1e = -1;
                #pragma unroll
                for (int e2 = 0; e2 < 32; e2++) {
                    unsigned int k = ((taken >> e2) & 1u) ? 0xFFFFFFFFu : kv[e2];
                    if (k < b0k)      { b1k = b0k; b1e = b0e; b0k = k; b0e = e2; }
                    else if (k < b1k) { b1k = k;   b1e = e2; }
                }
            }
        }
    }
    if (lane < K_PREF)
        g_prefix[(size_t)gw * K_PREF + lane] = (unsigned short)res;
}

// ---- chain: prefix in SMEM, bitmap in warp-0 registers --------------------
__global__ __launch_bounds__(128, 1)
void greedy_prefix_kernel(const float* __restrict__ dist,
                          float* __restrict__ out,
                          int B, int N, int write_len)
{
    __shared__ unsigned short s_pref[1024 * K_PREF];   // 32KB

    const int b    = blockIdx.x;
    const int tid  = threadIdx.x;
    const int lane = tid & 31;
    const int wid  = tid >> 5;

    {
        const uint4* src = (const uint4*)(g_prefix + (size_t)b * N * K_PREF);
        uint4* dst4 = (uint4*)s_pref;
        const int nvec = 2 * N;
        for (int i = tid; i < nvec; i += 128) dst4[i] = src[i];
    }
    __syncthreads();
    if (wid != 0) return;

    unsigned int word = g_bitmap[b * 32 + lane];
    const int C = g_C[b];
    int point = g_startc[b];

    const float* dbase = dist + (size_t)b * N * N;
    float* pred = out + (size_t)b * N;
    const float padf = (float)g_pad;

    for (int t = 0; t < C; t++) {
        unsigned int c = 0xFFFFu;
        if (lane < K_PREF) c = s_pref[point * K_PREF + lane];
        unsigned int w = __shfl_sync(0xffffffffu, word, (int)((c >> 5) & 31u));
        bool ok = (c < (unsigned)N) && !((w >> (c & 31u)) & 1u);
        unsigned int myk = ok ? (unsigned)lane : 64u;
        unsigned int ks = __reduce_min_sync(0xffffffffu, myk);

        unsigned int colstar;
        if (ks < 64u) {
            colstar = __shfl_sync(0xffffffffu, c, (int)ks);
        } else {
            const float* rp = dbase + (size_t)point * N;
            unsigned int bb = 0xFFFFFFFFu, bc = 0;
            #pragma unroll
            for (int q = 0; q < 8; q++) {
                int base = 32 * lane + 4 * q;
                if (base + 3 < N) {
                    float4 v = __ldg((const float4*)(rp + base));
                    const float* pv = (const float*)&v;
                    #pragma unroll
                    for (int r4 = 0; r4 < 4; r4++) {
                        if (!((word >> (4 * q + r4)) & 1u)) {
                            unsigned int sk = sortable(pv[r4]);
                            if (sk < bb) { bb = sk; bc = (unsigned)(base + r4); }
                        }
                    }
                }
            }
            unsigned int wm = __reduce_min_sync(0xffffffffu, bb);
            colstar = __reduce_min_sync(0xffffffffu,
                                        (bb == wm) ? bc : 0xFFFFFFFFu);
        }

        if (lane == 0) pred[t] = (float)colstar;
        if ((colstar >> 5) == (unsigned)lane) word |= 1u << (colstar & 31u);
        point = (int)colstar;
    }

    for (int t = C + lane; t < N; t += 32) pred[t] = padf;
    if (write_len && lane == 0) out[(size_t)B * N + b] = (float)C;
}

// ======== fallback path (non-conforming shapes): proven f32 chain ==========
__global__ void detect_kernel(const unsigned int* __restrict__ mw, int m_nwords,
                              const unsigned int* __restrict__ sw, int s_nwords,
                              const unsigned int* __restrict__ pw, int has_pad,
                              int N)
{
    __shared__ int sh[6];
    if (threadIdx.x < 6) sh[threadIdx.x] = 0;
    __syncthreads();
    int mk, sk, pad;
    detect_core(mw, m_nwords, sw, s_nwords, pw, has_pad, N,
                &mk, &sk, &pad, threadIdx.x, blockDim.x, sh);
    if (threadIdx.x == 0) { g_mask_kind = mk; g_start_kind = sk; g_pad = pad; }
}

__device__ __forceinline__ float4 ldg128_nc(const float* p) {
    float4 v;
    asm volatile("ld.global.nc.v4.f32 {%0,%1,%2,%3}, [%4];"
                 : "=f"(v.x), "=f"(v.y), "=f"(v.z), "=f"(v.w)
                 : "l"(p));
    return v;
}

__global__ __launch_bounds__(128, 1)
void greedy_f32_kernel(const float* __restrict__ dist,
                       const void*  __restrict__ mask,
                       const void*  __restrict__ start_idx,
                       float*       __restrict__ out,
                       int B, int N, int write_len)
{
    __shared__ unsigned long long sbuf[2][4];
    __shared__ int scnt[4];

    const int b    = blockIdx.x;
    const int tid  = threadIdx.x;
    const int lane = tid & 31;
    const int wid  = tid >> 5;
    const int mk   = g_mask_kind;
    const float padf = (float)g_pad;
    const int nf4  = N >> 2;
    const unsigned int BIGBITS = 0x49742400u;

    const bool v0 = (tid       < nf4);
    const bool v1 = (tid + 128 < nf4);

    unsigned int m = 0;
    #pragma unroll
    for (int s = 0; s < 2; s++) {
        #pragma unroll
        for (int r = 0; r < 4; r++) {
            int col = 4 * (tid + 128 * s) + r;
            bool mb = true;
            if (col < N) mb = mask_at(mask, mk, b * N + col);
            if (mb) m |= 1u << (s * 4 + r);
        }
    }

    {
        unsigned int cnt = 8u - (unsigned)__popc(m);
        cnt = __reduce_add_sync(0xffffffffu, cnt);
        if (lane == 0) scnt[wid] = (int)cnt;
    }
    __syncthreads();
    const int C = scnt[0] + scnt[1] + scnt[2] + scnt[3];

    int point = read_start_k(start_idx, g_start_kind, b);
    if (point < 0) point = 0;
    if (point >= N) point = N - 1;

    const float* dbase = dist + (size_t)b * N * N;
    float* pred = out + (size_t)b * N;

    for (int t = 0; t < C; t++) {
        const float* rp = dbase + (size_t)point * N;

        float4 a = v0 ? ldg128_nc(rp + 4 * tid)
                      : make_float4(1e6f, 1e6f, 1e6f, 1e6f);
        float4 c = v1 ? ldg128_nc(rp + 4 * (tid + 128))
                      : make_float4(1e6f, 1e6f, 1e6f, 1e6f);

        unsigned int bb = BIGBITS, bc = 0;
        const float* pa = (const float*)&a;
        const float* pc = (const float*)&c;
        #pragma unroll
        for (int r = 0; r < 4; r++) {
            unsigned int fb = ((m >> r) & 1u) ? BIGBITS : __float_as_uint(pa[r]);
            if (fb < bb) { bb = fb; bc = 4 * tid + r; }
        }
        #pragma unroll
        for (int r = 0; r < 4; r++) {
            unsigned int fb = ((m >> (4 + r)) & 1u) ? BIGBITS : __float_as_uint(pc[r]);
            if (fb < bb) { bb = fb; bc = 4 * (tid + 128) + r; }
        }

        unsigned int wmin = __reduce_min_sync(0xffffffffu, bb);
        unsigned int colc = (bb == wmin) ? bc : 0xFFFFFFFFu;
        unsigned int wcol = __reduce_min_sync(0xffffffffu, colc);

        if (lane == 0)
            sbuf[t & 1][wid] = ((unsigned long long)wmin << 32) | wcol;
        __syncthreads();
        unsigned long long k0 = sbuf[t & 1][0], k1 = sbuf[t & 1][1];
        unsigned long long k2 = sbuf[t & 1][2], k3 = sbuf[t & 1][3];
        unsigned long long ka = k0 < k1 ? k0 : k1;
        unsigned long long kb = k2 < k3 ? k2 : k3;
        unsigned long long k  = ka < kb ? ka : kb;

        int idx = (int)(unsigned int)k;
        if (tid == 0) pred[t] = (float)idx;

        int f = idx >> 2;
        if ((f & 127) == tid)
            m |= 1u << (((f >> 7) << 2) | (idx & 3));
        point = idx;
    }

    for (int t = C + tid; t < N; t += 128) pred[t] = padf;
    if (write_len && tid == 0) out[(size_t)B * N + b] = (float)C;
}

extern "C" void kernel_launch(void* const* d_in, const int* in_sizes, int n_in,
                              void* d_out, int out_size)
{
    // identify inputs by element count (order-proof)
    int di = 0, mi = -1, si = -1, pi = -1;
    for (int i = 1; i < n_in; i++)
        if (in_sizes[i] > in_sizes[di]) di = i;
    for (int i = 0; i < n_in; i++) {
        if (i == di) continue;
        if (pi < 0 || in_sizes[i] < in_sizes[pi]) pi = i;
    }
    for (int i = 0; i < n_in; i++) {
        if (i == di || i == pi) continue;
        if (mi < 0) { mi = i; continue; }
        si = i;
    }
    if (si >= 0 && in_sizes[si] > in_sizes[mi]) { int t = mi; mi = si; si = t; }
    if (si < 0) { si = pi; pi = -1; }

    const float* dist  = (const float*)d_in[di];
    const void*  mask  = d_in[mi];
    const void*  start = d_in[si];
    const void*  padp  = (pi >= 0) ? d_in[pi] : nullptr;

    const int B = in_sizes[si];
    const int N = in_sizes[mi] / B;

    int m_nwords = in_sizes[mi] / 4;
    if (m_nwords > 2048) m_nwords = 2048;
    int s_nwords = in_sizes[si];

    int write_len = (out_size >= B * N + B) ? 1 : 0;

    bool fast_ok = (N % 4 == 0) && (N >= 4) && (N <= 1024) && (B <= MAXB) &&
                   ((long long)B * N <= 16777216LL / K_PREF);
    if (fast_ok) {
        prep_kernel<<<B, 256>>>(mask, start,
                                padp ? (const unsigned int*)padp
                                     : (const unsigned int*)start,
                                padp ? 1 : 0, m_nwords, s_nwords, B, N);
        build_prefix_kernel<<<(B * N + 7) / 8, 256>>>(dist, B, N);
        greedy_prefix_kernel<<<B, 128>>>(dist, (float*)d_out, B, N, write_len);
    } else {
        detect_kernel<<<1, 256>>>((const unsigned int*)mask, m_nwords,
                                  (const unsigned int*)start, s_nwords,
                                  padp ? (const unsigned int*)padp
                                       : (const unsigned int*)start,
                                  padp ? 1 : 0, N);
        greedy_f32_kernel<<<B, 128>>>(dist, mask, start, (float*)d_out,
                                      B, N, write_len);
    }
}